// round 4
// baseline (speedup 1.0000x reference)
#include <cuda_runtime.h>
#include <stdint.h>

// EmbeddingDropout: out[r, :] = weight[x[r], :] * mask[x[r]]
// x: [16384] int32, weight: [50257, 512] f32, mask: [50257] f32.
// Output: [16384, 512] f32.
//
// R4: latency-limited (issue 9.7%, nothing saturated). One warp handles TWO
// rows: both index chains overlap, 8 independent LDG.128 in flight per
// thread-quantum (4 KB/warp). Streaming stores for the write-once output.

#define D 512
#define D4 (D / 4)                 // 128 float4 per row
#define THREADS 256                // 8 warps
#define ROWS_PER_WARP 2
#define ROWS_PER_BLOCK ((THREADS / 32) * ROWS_PER_WARP)   // 16

__global__ __launch_bounds__(THREADS) void embedding_dropout_kernel(
    const int* __restrict__ x,           // [N]
    const float4* __restrict__ weight,   // [V, D4]
    const float* __restrict__ mask,      // [V]
    float4* __restrict__ out,            // [N, D4]
    int n_rows)
{
    int warp = (blockIdx.x * THREADS + threadIdx.x) >> 5;
    int lane = threadIdx.x & 31;
    int row0 = warp * ROWS_PER_WARP;
    int row1 = row0 + 1;
    if (row0 >= n_rows) return;
    bool has1 = (row1 < n_rows);

    // Both index chains launch immediately and overlap.
    int idx0 = __ldg(&x[row0]);
    int idx1 = has1 ? __ldg(&x[row1]) : idx0;

    float s0 = __ldg(&mask[idx0]);
    float s1 = __ldg(&mask[idx1]);

    const float4* w0 = weight + (size_t)idx0 * D4;
    const float4* w1 = weight + (size_t)idx1 * D4;

    float4 a[4], b[4];
    #pragma unroll
    for (int i = 0; i < 4; i++) a[i] = __ldg(&w0[lane + 32 * i]);
    #pragma unroll
    for (int i = 0; i < 4; i++) b[i] = __ldg(&w1[lane + 32 * i]);

    float4* o0 = out + (size_t)row0 * D4;
    #pragma unroll
    for (int i = 0; i < 4; i++) {
        a[i].x *= s0; a[i].y *= s0; a[i].z *= s0; a[i].w *= s0;
        __stcs(&o0[lane + 32 * i], a[i]);
    }
    if (has1) {
        float4* o1 = out + (size_t)row1 * D4;
        #pragma unroll
        for (int i = 0; i < 4; i++) {
            b[i].x *= s1; b[i].y *= s1; b[i].z *= s1; b[i].w *= s1;
            __stcs(&o1[lane + 32 * i], b[i]);
        }
    }
}

extern "C" void kernel_launch(void* const* d_in, const int* in_sizes, int n_in,
                              void* d_out, int out_size)
{
    // Identify inputs by element count: x=16384, weight=25731584, mask=50257.
    long long max_sz = -1, mid_sz = -1;
    int wi = -1, mi = -1, xi = -1;
    for (int i = 0; i < n_in; i++)
        if (in_sizes[i] > max_sz) { max_sz = in_sizes[i]; wi = i; }
    for (int i = 0; i < n_in; i++)
        if (i != wi && in_sizes[i] > mid_sz) { mid_sz = in_sizes[i]; mi = i; }
    for (int i = 0; i < n_in; i++)
        if (i != wi && i != mi) { xi = i; break; }

    const int*    x    = (const int*)d_in[xi];
    const float4* w    = (const float4*)d_in[wi];
    const float*  mask = (const float*)d_in[mi];
    float4*       out  = (float4*)d_out;
    int n_rows = in_sizes[xi];

    int blocks = (n_rows + ROWS_PER_BLOCK - 1) / ROWS_PER_BLOCK;
    embedding_dropout_kernel<<<blocks, THREADS>>>(x, w, mask, out, n_rows);
}